// round 16
// baseline (speedup 1.0000x reference)
#include <cuda_runtime.h>
#include <cuda_fp16.h>
#include <math.h>
#include <stdint.h>

#define NB 8
#define SL 8192
#define ED 512
#define NH 8
#define DH 64
#define MT (NB*SL)

// ---------------- scratch (device globals; no allocation) -------------------
__device__ float g_kv[NB * NH * DH * DH];
__device__ float g_ksum[NB * NH * DH];
__device__ __half g_qh[(size_t)MT * ED];
__device__ __half g_k16[(size_t)MT * ED];
__device__ __half g_v16[(size_t)MT * ED];
__device__ __half g_ao[(size_t)MT * ED];
__device__ __half g_w16[4][ED * ED];
__device__ __half g_kvah[NB * NH * 80 * 64];
__device__ __half g_kval[NB * NH * 80 * 64];

// ---------------- helpers ---------------------------------------------------
__device__ __forceinline__ uint32_t smem_u32(const void* p) {
    uint32_t a;
    asm("{ .reg .u64 t; cvta.to.shared.u64 t, %1; cvt.u32.u64 %0, t; }" : "=r"(a) : "l"(p));
    return a;
}
__device__ __forceinline__ uint32_t pack2h(__half a, __half b) {
    __half2 t(a, b);
    return *reinterpret_cast<uint32_t*>(&t);
}
__device__ __forceinline__ void cp16(uint32_t s, const void* g) {
    asm volatile("cp.async.cg.shared.global [%0], [%1], 16;" :: "r"(s), "l"(g));
}
#define CP_COMMIT() asm volatile("cp.async.commit_group;" ::: "memory")
#define CP_WAIT(N)  asm volatile("cp.async.wait_group %0;" :: "n"(N) : "memory")

#define LDSM4(r, addr)                                                         \
    asm volatile("ldmatrix.sync.aligned.m8n8.x4.shared.b16 {%0,%1,%2,%3}, [%4];" \
        : "=r"((r)[0]), "=r"((r)[1]), "=r"((r)[2]), "=r"((r)[3]) : "r"(addr))

__device__ __forceinline__ uint32_t movm(uint32_t a) {
    uint32_t d;
    asm volatile("movmatrix.sync.aligned.m8n8.trans.b16 %0, %1;" : "=r"(d) : "r"(a));
    return d;
}

#define MMA16816(d, a, b0, b1)                                                 \
    asm volatile("mma.sync.aligned.m16n8k16.row.col.f32.f16.f16.f32 "          \
        "{%0,%1,%2,%3}, {%4,%5,%6,%7}, {%8,%9}, {%0,%1,%2,%3};"                \
        : "+f"((d)[0]), "+f"((d)[1]), "+f"((d)[2]), "+f"((d)[3])               \
        : "r"((a)[0]), "r"((a)[1]), "r"((a)[2]), "r"((a)[3]), "r"(b0), "r"(b1))

// ---------------- fused weight convert: all 4 W in one launch -----------------
__global__ __launch_bounds__(256) void conv4_kernel(const float* __restrict__ w0,
                                                    const float* __restrict__ w1,
                                                    const float* __restrict__ w2,
                                                    const float* __restrict__ w3,
                                                    int n4)
{
    const int wsel = blockIdx.y;
    const float* src = (wsel == 0) ? w0 : (wsel == 1) ? w1 : (wsel == 2) ? w2 : w3;
    __half* dst = g_w16[wsel];
    int i = blockIdx.x * blockDim.x + threadIdx.x;
    if (i >= n4) return;
    float4 v = ((const float4*)src)[i];
    uint2 p;
    p.x = pack2h(__float2half_rn(v.x), __float2half_rn(v.y));
    p.y = pack2h(__float2half_rn(v.z), __float2half_rn(v.w));
    ((uint2*)dst)[i] = p;
}

// ---------------- shared GEMM fragment compute --------------------------------
__device__ __forceinline__ void gemm_compute_chunk(uint32_t sA, uint32_t sB,
                                                   int lane, int wm, int wn,
                                                   float acc[2][8][4])
{
    uint32_t fa[2][2][4];
    uint32_t fb[2][4];

    #define LOAD_A(s16, buf)                                                   \
    {                                                                          \
        _Pragma("unroll")                                                      \
        for (int mf = 0; mf < 2; mf++) {                                       \
            const int arow = wm * 32 + mf * 16 + (lane & 15);                  \
            const int achk = (s16) * 2 + (lane >> 4);                          \
            LDSM4(fa[buf][mf], sA + arow * 128 + ((achk ^ (arow & 7)) << 4));  \
        }                                                                      \
    }
    #define LOAD_B(s16, nf, buf)                                               \
    {                                                                          \
        const int brow = wn * 64 + (nf) * 16 + (lane & 7) + ((lane >> 4) << 3);\
        const int bchk = (s16) * 2 + ((lane >> 3) & 1);                        \
        LDSM4(fb[buf], sB + brow * 128 + ((bchk ^ (brow & 7)) << 4));          \
    }

    LOAD_A(0, 0);
    LOAD_B(0, 0, 0);

#pragma unroll
    for (int s16 = 0; s16 < 4; s16++) {
        const int ab = s16 & 1;
#pragma unroll
        for (int nf = 0; nf < 4; nf++) {
            const int bb = nf & 1;
            if (nf < 3) {
                LOAD_B(s16, nf + 1, bb ^ 1);
            } else if (s16 < 3) {
                LOAD_A(s16 + 1, ab ^ 1);
                LOAD_B(s16 + 1, 0, bb ^ 1);
            }
#pragma unroll
            for (int mf = 0; mf < 2; mf++) {
                MMA16816(acc[mf][2 * nf],     fa[ab][mf], fb[bb][0], fb[bb][1]);
                MMA16816(acc[mf][2 * nf + 1], fa[ab][mf], fb[bb][2], fb[bb][3]);
            }
        }
    }
    #undef LOAD_A
    #undef LOAD_B
}

// ---------------- f32-A fused-convert GEMM (proven R14) -----------------------
#define RAW2_OFF 0
#define AH2_OFF  32768
#define B2_OFF   49152
#define STAGE2   81920
#define GSMEM2   (2 * STAGE2)

__device__ __forceinline__ void issue_f32(uint32_t st, const float* __restrict__ A,
                                          const __half* __restrict__ Bh,
                                          int bm, int bn, int ch, int tid)
{
    const int kc = ch * 64;
#pragma unroll
    for (int i = 0; i < 4; i++) {
        const int idx = tid + i * 512;
        const int row = idx >> 4;
        const int c16 = idx & 15;
        cp16(st + RAW2_OFF + idx * 16,
             A + (size_t)(bm + row) * ED + kc + c16 * 4);
    }
#pragma unroll
    for (int i = 0; i < 4; i++) {
        const int idx = tid + i * 512;
        const int row = idx >> 3;
        const int c = idx & 7;
        cp16(st + B2_OFF + row * 128 + ((c ^ (row & 7)) << 4),
             Bh + (size_t)(bn + row) * ED + kc + c * 8);
    }
    CP_COMMIT();
}

__device__ __forceinline__ void convert_own(char* smem_raw, uint32_t stoff, int tid)
{
#pragma unroll
    for (int i = 0; i < 4; i++) {
        const int idx = tid + i * 512;
        const int row = idx >> 4;
        const int c16 = idx & 15;
        float4 v = *(const float4*)(smem_raw + stoff + RAW2_OFF + idx * 16);
        uint2 p;
        p.x = pack2h(__float2half_rn(v.x), __float2half_rn(v.y));
        p.y = pack2h(__float2half_rn(v.z), __float2half_rn(v.w));
        const int c8 = c16 >> 1;
        const uint32_t soff = row * 128 + ((c8 ^ (row & 7)) << 4) + (c16 & 1) * 8;
        *(uint2*)(smem_raw + stoff + AH2_OFF + soff) = p;
    }
}

template <int FEAT>
__device__ __forceinline__ void gemm_f32_body(const float* __restrict__ A,
                                              const __half* __restrict__ Bh,
                                              const float* __restrict__ bias,
                                              __half* __restrict__ Ch,
                                              char* smem_raw)
{
    const uint32_t sb = smem_u32(smem_raw);
    const int tid = threadIdx.x;
    const int lane = tid & 31;
    const int wid = tid >> 5;
    const int wm = wid >> 2;
    const int wn = wid & 3;
    const int bm = blockIdx.y * 128;
    const int bn = blockIdx.x * 256;

    float acc[2][8][4];
#pragma unroll
    for (int i = 0; i < 2; i++)
#pragma unroll
        for (int j = 0; j < 8; j++)
#pragma unroll
            for (int q = 0; q < 4; q++) acc[i][j][q] = 0.f;

    issue_f32(sb, A, Bh, bm, bn, 0, tid);
    issue_f32(sb + STAGE2, A, Bh, bm, bn, 1, tid);

#pragma unroll 1
    for (int ch = 0; ch < 8; ch++) {
        const uint32_t stoff = (ch & 1) * STAGE2;
        if (ch < 7) { CP_WAIT(1); } else { CP_WAIT(0); }
        convert_own(smem_raw, stoff, tid);
        __syncthreads();
        gemm_compute_chunk(sb + stoff + AH2_OFF, sb + stoff + B2_OFF,
                           lane, wm, wn, acc);
        __syncthreads();
        if (ch + 2 < 8) issue_f32(sb + stoff, A, Bh, bm, bn, ch + 2, tid);
    }

#pragma unroll
    for (int mf = 0; mf < 2; mf++) {
        const int row0 = bm + wm * 32 + mf * 16 + (lane >> 2);
#pragma unroll
        for (int nf8 = 0; nf8 < 8; nf8++) {
            const int col = bn + wn * 64 + nf8 * 8 + (lane & 3) * 2;
            const float b0 = bias[col], b1 = bias[col + 1];
            float x0 = acc[mf][nf8][0] + b0;
            float x1 = acc[mf][nf8][1] + b1;
            float x2 = acc[mf][nf8][2] + b0;
            float x3 = acc[mf][nf8][3] + b1;
            if (FEAT) {
                x0 = (x0 > 0.f) ? (x0 + 1.f) : expf(x0);
                x1 = (x1 > 0.f) ? (x1 + 1.f) : expf(x1);
                x2 = (x2 > 0.f) ? (x2 + 1.f) : expf(x2);
                x3 = (x3 > 0.f) ? (x3 + 1.f) : expf(x3);
            }
            *(uint32_t*)&Ch[(size_t)row0 * ED + col] =
                pack2h(__float2half_rn(x0), __float2half_rn(x1));
            *(uint32_t*)&Ch[(size_t)(row0 + 8) * ED + col] =
                pack2h(__float2half_rn(x2), __float2half_rn(x3));
        }
    }
}

__global__ __launch_bounds__(512, 1) void gemm_q_f32(const float* __restrict__ A,
                                                     const __half* __restrict__ Bh,
                                                     const float* __restrict__ bias,
                                                     __half* __restrict__ Ch)
{
    extern __shared__ char smem_raw[];
    gemm_f32_body<1>(A, Bh, bias, Ch, smem_raw);
}

__global__ __launch_bounds__(512, 1) void gemm_kv_f32(const float* __restrict__ Ak,
                                                      const float* __restrict__ Av,
                                                      const __half* __restrict__ Bk,
                                                      const __half* __restrict__ Bv,
                                                      const float* __restrict__ biask,
                                                      const float* __restrict__ biasv,
                                                      __half* __restrict__ Ck,
                                                      __half* __restrict__ Cv)
{
    extern __shared__ char smem_raw[];
    if (blockIdx.z == 0)
        gemm_f32_body<1>(Ak, Bk, biask, Ck, smem_raw);
    else
        gemm_f32_body<0>(Av, Bv, biasv, Cv, smem_raw);
}

// ---------------- fp16-A GEMM for output (proven, 3-stage; row offset) --------
#define A_OFF    0
#define B_OFF    16384
#define STAGE_SZ 49152
#define GSMEM    (3 * STAGE_SZ)

__device__ __forceinline__ void issue_loads(uint32_t st,
                                            const __half* __restrict__ A16,
                                            const __half* __restrict__ Bh,
                                            int bm, int bn, int ch, int tid)
{
    const int kc = ch * 64;
#pragma unroll
    for (int i = 0; i < 2; i++) {
        const int idx = tid + i * 512;
        const int row = idx >> 3;
        const int c = idx & 7;
        cp16(st + A_OFF + row * 128 + ((c ^ (row & 7)) << 4),
             A16 + (size_t)(bm + row) * ED + kc + c * 8);
    }
#pragma unroll
    for (int i = 0; i < 4; i++) {
        const int idx = tid + i * 512;
        const int row = idx >> 3;
        const int c = idx & 7;
        cp16(st + B_OFF + row * 128 + ((c ^ (row & 7)) << 4),
             Bh + (size_t)(bn + row) * ED + kc + c * 8);
    }
    CP_COMMIT();
}

__global__ __launch_bounds__(512, 1) void gemm_out(const __half* __restrict__ A16,
                                                   const __half* __restrict__ Bh,
                                                   const float* __restrict__ bias,
                                                   float* __restrict__ C,
                                                   int my0)
{
    extern __shared__ char smem_raw[];
    const uint32_t sb = smem_u32(smem_raw);
    const int tid = threadIdx.x;
    const int lane = tid & 31;
    const int wid = tid >> 5;
    const int wm = wid >> 2;
    const int wn = wid & 3;
    const int bm = (blockIdx.y + my0) * 128;
    const int bn = blockIdx.x * 256;

    float acc[2][8][4];
#pragma unroll
    for (int i = 0; i < 2; i++)
#pragma unroll
        for (int j = 0; j < 8; j++)
#pragma unroll
            for (int q = 0; q < 4; q++) acc[i][j][q] = 0.f;

    issue_loads(sb, A16, Bh, bm, bn, 0, tid);
    issue_loads(sb + STAGE_SZ, A16, Bh, bm, bn, 1, tid);

#pragma unroll 1
    for (int ch = 0; ch < 8; ch++) {
        if (ch < 7) { CP_WAIT(1); } else { CP_WAIT(0); }
        __syncthreads();
        if (ch < 6)
            issue_loads(sb + ((ch + 2) % 3) * STAGE_SZ, A16, Bh, bm, bn, ch + 2, tid);
        const uint32_t cur = sb + (ch % 3) * STAGE_SZ;
        gemm_compute_chunk(cur + A_OFF, cur + B_OFF, lane, wm, wn, acc);
    }

#pragma unroll
    for (int mf = 0; mf < 2; mf++) {
        const int row0 = bm + wm * 32 + mf * 16 + (lane >> 2);
#pragma unroll
        for (int nf8 = 0; nf8 < 8; nf8++) {
            const int col = bn + wn * 64 + nf8 * 8 + (lane & 3) * 2;
            const float b0 = bias[col], b1 = bias[col + 1];
            *(float2*)&C[(size_t)row0 * ED + col] =
                make_float2(acc[mf][nf8][0] + b0, acc[mf][nf8][1] + b1);
            *(float2*)&C[(size_t)(row0 + 8) * ED + col] =
                make_float2(acc[mf][nf8][2] + b0, acc[mf][nf8][3] + b1);
        }
    }
}

// ---------------- zeroing ----------------------------------------------------
__global__ void zero_small()
{
    int i = blockIdx.x * blockDim.x + threadIdx.x;
    if (i < NB * NH * DH * DH) g_kv[i] = 0.f;
    if (i < NB * NH * DH)      g_ksum[i] = 0.f;
}

// ---------------- tensorized KV via movmatrix (proven R12) --------------------
#define KV2_K 0
#define KV2_V 8192
#define KV2_STAGE 16384
#define KV2_SMEM  32768

__device__ __forceinline__ void kv_issue(uint32_t sb, int stage, int n, int h,
                                         int s0, int tid)
{
#pragma unroll
    for (int it = 0; it < 4; it++) {
        const int idx = tid + it * 256;
        const int t = idx >> 9;
        const int r = (idx >> 3) & 63;
        const int c = idx & 7;
        const __half* src = t ? g_v16 : g_k16;
        cp16(sb + stage * KV2_STAGE + t * 8192 + r * 128 + ((c ^ (r & 7)) << 4),
             src + (size_t)(n * SL + s0 + r) * ED + h * DH + c * 8);
    }
    CP_COMMIT();
}

__global__ __launch_bounds__(256) void kv_kernel()
{
    extern __shared__ char smem_raw[];
    const uint32_t sb = smem_u32(smem_raw);
    const int tid = threadIdx.x;
    const int lane = tid & 31;
    const int wid = tid >> 5;
    const int wm = wid & 3;
    const int wn = wid >> 2;
    const int sp = blockIdx.x;
    const int h = blockIdx.y;
    const int n = blockIdx.z;
    const int nh = n * NH + h;
    const int s_base = sp * (SL / 8);

    float acc[4][4];
#pragma unroll
    for (int j = 0; j < 4; j++)
#pragma unroll
        for (int q = 0; q < 4; q++) acc[j][q] = 0.f;
    float ks = 0.f;
    const int sum_d = tid & 63;
    const int sum_p = tid >> 6;

    kv_issue(sb, 0, n, h, s_base, tid);

#pragma unroll 1
    for (int it = 0; it < 16; it++) {
        if (it < 15) { kv_issue(sb, (it + 1) & 1, n, h, s_base + (it + 1) * 64, tid); CP_WAIT(1); }
        else CP_WAIT(0);
        __syncthreads();
        const uint32_t st = sb + (it & 1) * KV2_STAGE;
        char* stc = smem_raw + (it & 1) * KV2_STAGE;

#pragma unroll
        for (int kstep = 0; kstep < 4; kstep++) {
            uint32_t vr[4], fa[4];
            {
                const int arow = kstep * 16 + (lane & 15);
                const int achk = wm * 2 + (lane >> 4);
                LDSM4(vr, st + KV2_V + arow * 128 + ((achk ^ (arow & 7)) << 4));
                fa[0] = movm(vr[0]); fa[1] = movm(vr[2]);
                fa[2] = movm(vr[1]); fa[3] = movm(vr[3]);
            }
#pragma unroll
            for (int p = 0; p < 2; p++) {
                uint32_t kr[4];
                const int brow = kstep * 16 + (lane & 15);
                const int bchk = wn * 4 + p * 2 + (lane >> 4);
                LDSM4(kr, st + KV2_K + brow * 128 + ((bchk ^ (brow & 7)) << 4));
                uint32_t b00 = movm(kr[0]), b01 = movm(kr[1]);
                uint32_t b10 = movm(kr[2]), b11 = movm(kr[3]);
                MMA16816(acc[p * 2],     fa, b00, b01);
                MMA16816(acc[p * 2 + 1], fa, b10, b11);
            }
        }
#pragma unroll
        for (int rr = 0; rr < 16; rr++) {
            const int r = sum_p * 16 + rr;
            uint32_t off = r * 128 + sum_d * 2;
            uint32_t sw = off ^ ((off >> 3) & 0x70);
            ks += __half2float(*(__half*)(stc + KV2_K + sw));
        }
        __syncthreads();
    }

    const int g = lane >> 2, tig = lane & 3;
    float* kvout = g_kv + nh * 4096;
#pragma unroll
    for (int j = 0; j < 4; j++) {
        const int d = wn * 32 + j * 8 + tig * 2;
        const int m = wm * 16 + g;
        atomicAdd(&kvout[m * 64 + d],           acc[j][0]);
        atomicAdd(&kvout[m * 64 + d + 1],       acc[j][1]);
        atomicAdd(&kvout[(m + 8) * 64 + d],     acc[j][2]);
        atomicAdd(&kvout[(m + 8) * 64 + d + 1], acc[j][3]);
    }
    atomicAdd(&g_ksum[nh * 64 + sum_d], ks);
}

// ---------------- KV finalize -------------------------------------------------
__global__ __launch_bounds__(256) void kv_finalize()
{
    const int nh = blockIdx.x;
    const float* kv = g_kv + nh * 4096;
    const float* ks = g_ksum + nh * 64;
    char* oh = (char*)g_kvah + (size_t)nh * 10240;
    char* ol = (char*)g_kval + (size_t)nh * 10240;
    for (int idx = threadIdx.x; idx < 80 * 64; idx += 256) {
        const int r = idx >> 6, d = idx & 63;
        float x = (r < 64) ? kv[r * 64 + d] : (r == 64 ? ks[d] : 0.f);
        __half hh = __float2half_rn(x);
        __half ll = __float2half_rn(x - __half2float(hh));
        uint32_t off = r * 128 + d * 2;
        uint32_t sw = off ^ ((off >> 3) & 0x70);
        *(__half*)(oh + sw) = hh;
        *(__half*)(ol + sw) = ll;
    }
}

// ---------------- tensorized attn (proven R13; batch offset) ------------------
#define AT_Q  0
#define AT_BH 16384
#define AT_BL 26624
#define AT_SMEM 36864

__global__ __launch_bounds__(256) void attn_kernel(int n0)
{
    extern __shared__ char smem_raw[];
    const uint32_t sb = smem_u32(smem_raw);
    const int tid = threadIdx.x;
    const int lane = tid & 31;
    const int wid = tid >> 5;
    const int l0 = blockIdx.x * 128;
    const int h = blockIdx.y;
    const int n = blockIdx.z + n0;
    const int nh = n * NH + h;

#pragma unroll
    for (int it = 0; it < 4; it++) {
        int idx = tid + it * 256;
        int r = idx >> 3;
        int c = idx & 7;
        cp16(sb + AT_Q + r * 128 + ((c ^ (r & 7)) << 4),
             g_qh + (size_t)(n * SL + l0 + r) * ED + h * DH + c * 8);
    }
#pragma unroll
    for (int it = 0; it < 5; it++) {
        int idx = tid + it * 256;
        int buf = idx >= 640;
        int ch = buf ? idx - 640 : idx;
        cp16(sb + (buf ? AT_BL : AT_BH) + ch * 16,
             (buf ? g_kval : g_kvah) + (size_t)nh * 5120 + ch * 8);
    }
    CP_COMMIT();
    CP_WAIT(0);
    __syncthreads();

    float acc[9][4];
#pragma unroll
    for (int j = 0; j < 9; j++)
#pragma unroll
        for (int q = 0; q < 4; q++) acc[j][q] = 0.f;

#pragma unroll
    for (int kstep = 0; kstep < 4; kstep++) {
        uint32_t fah[4];
        {
            const int arow = wid * 16 + (lane & 15);
            const int achk = kstep * 2 + (lane >> 4);
            LDSM4(fah, sb + AT_Q + arow * 128 + ((achk ^ (arow & 7)) << 4));
        }
        uint32_t fbh[5][4], fbl[5][4];
#pragma unroll
        for (int p = 0; p < 5; p++) {
            const int brow = p * 16 + (lane & 7) + ((lane >> 4) << 3);
            const int bchk = kstep * 2 + ((lane >> 3) & 1);
            const uint32_t boff = brow * 128 + ((bchk ^ (brow & 7)) << 4);
            LDSM4(fbh[p], sb + AT_BH + boff);
            LDSM4(fbl[p], sb + AT_BL + boff);
        }
#pragma unroll
        for (int j = 0; j < 9; j++) {
            uint32_t bh0 = fbh[j >> 1][(j & 1) * 2], bh1 = fbh[j >> 1][(j & 1) * 2 + 1];
            uint32_t bl0 = fbl[j >> 1][(j & 1) * 2], bl1 = fbl[j >> 1][(j & 1) * 2 + 1];
            MMA16816(acc[j], fah, bh0, bh1);
            MMA16816(acc[j], fah, bl0, bl1);
        }
    }

    const float zd0 = __shfl_sync(0xFFFFFFFFu, acc[8][0], lane & ~3);
    const float zd1 = __shfl_sync(0xFFFFFFFFu, acc[8][2], lane & ~3);
    const float z0 = 1.f / (fmaxf(zd0, 0.f) + 1e-6f);
    const float z1 = 1.f / (fmaxf(zd1, 0.f) + 1e-6f);
    const int g = lane >> 2, tig = lane & 3;
    const int row0 = l0 + wid * 16 + g;

#pragma unroll
    for (int j = 0; j < 8; j++) {
        const int e = h * DH + j * 8 + tig * 2;
        float x0 = acc[j][0] * z0, x1 = acc[j][1] * z0;
        float x2 = acc[j][2] * z1, x3 = acc[j][3] * z1;
        *(uint32_t*)&g_ao[(size_t)(n * SL + row0) * ED + e] =
            pack2h(__float2half_rn(x0), __float2half_rn(x1));
        *(uint32_t*)&g_ao[(size_t)(n * SL + row0 + 8) * ED + e] =
            pack2h(__float2half_rn(x2), __float2half_rn(x3));
    }
}

// ---------------- launch -----------------------------------------------------
extern "C" void kernel_launch(void* const* d_in, const int* in_sizes, int n_in,
                              void* d_out, int out_size)
{
    const float* q_in = (const float*)d_in[0];
    const float* k_in = (const float*)d_in[1];
    const float* v_in = (const float*)d_in[2];
    const float* Wq = (const float*)d_in[3];
    const float* bq = (const float*)d_in[4];
    const float* Wk = (const float*)d_in[5];
    const float* bk = (const float*)d_in[6];
    const float* Wv = (const float*)d_in[7];
    const float* bv = (const float*)d_in[8];
    const float* Wo = (const float*)d_in[9];
    const float* bo = (const float*)d_in[10];
    float* out = (float*)d_out;

    __half *qh, *k16, *v16, *ao, *w16;
    cudaGetSymbolAddress((void**)&qh, g_qh);
    cudaGetSymbolAddress((void**)&k16, g_k16);
    cudaGetSymbolAddress((void**)&v16, g_v16);
    cudaGetSymbolAddress((void**)&ao, g_ao);
    cudaGetSymbolAddress((void**)&w16, g_w16);
    __half* wq16 = w16;
    __half* wk16 = w16 + (size_t)ED * ED;
    __half* wv16 = w16 + (size_t)2 * ED * ED;
    __half* wo16 = w16 + (size_t)3 * ED * ED;

    static cudaStream_t s1, s3;
    static cudaEvent_t ev0, evW, evGQ, evKV, evA1;
    static bool inited = false;
    if (!inited) {
        cudaStreamCreateWithFlags(&s1, cudaStreamNonBlocking);
        cudaStreamCreateWithFlags(&s3, cudaStreamNonBlocking);
        cudaEventCreateWithFlags(&ev0, cudaEventDisableTiming);
        cudaEventCreateWithFlags(&evW, cudaEventDisableTiming);
        cudaEventCreateWithFlags(&evGQ, cudaEventDisableTiming);
        cudaEventCreateWithFlags(&evKV, cudaEventDisableTiming);
        cudaEventCreateWithFlags(&evA1, cudaEventDisableTiming);
        cudaFuncSetAttribute(gemm_q_f32,  cudaFuncAttributeMaxDynamicSharedMemorySize, GSMEM2);
        cudaFuncSetAttribute(gemm_kv_f32, cudaFuncAttributeMaxDynamicSharedMemorySize, GSMEM2);
        cudaFuncSetAttribute(gemm_out,    cudaFuncAttributeMaxDynamicSharedMemorySize, GSMEM);
        cudaFuncSetAttribute(kv_kernel,   cudaFuncAttributeMaxDynamicSharedMemorySize, KV2_SMEM);
        cudaFuncSetAttribute(attn_kernel, cudaFuncAttributeMaxDynamicSharedMemorySize, AT_SMEM);
        inited = true;
    }

    const int n4w = ED * ED / 4;
    dim3 blk(256);
    dim3 gblk(512);
    dim3 gg(ED / 256, MT / 128);
    dim3 gg2(ED / 256, MT / 128, 2);
    dim3 ggh(ED / 256, MT / 256);          // half of the M rows

    // fork: single fused weight-convert launch + zero on side stream
    cudaEventRecord(ev0, 0);
    cudaStreamWaitEvent(s3, ev0, 0);
    cudaStreamWaitEvent(s1, ev0, 0);
    conv4_kernel<<<dim3((n4w + 255) / 256, 4), blk, 0, s3>>>(Wq, Wk, Wv, Wo, n4w);
    zero_small<<<(NB * NH * DH * DH + 255) / 256, 256, 0, s3>>>();
    cudaEventRecord(evW, s3);

    // main: gemmKV first (kv depends on it)
    cudaStreamWaitEvent(0, evW, 0);
    gemm_kv_f32<<<gg2, gblk, GSMEM2>>>(k_in, v_in, wk16, wv16, bk, bv, k16, v16);

    // s1: gemmQ concurrent — kv+finalize hide under its tail
    cudaStreamWaitEvent(s1, evW, 0);
    gemm_q_f32<<<gg, gblk, GSMEM2, s1>>>(q_in, wq16, bq, qh);
    cudaEventRecord(evGQ, s1);

    // main: kv + finalize (overlap gemmQ)
    kv_kernel<<<dim3(8, NH, NB), blk, KV2_SMEM>>>();
    kv_finalize<<<NB * NH, blk>>>();
    cudaEventRecord(evKV, 0);

    // s1 (after gemmQ in-order): attn for batches 4..7, overlaps attn c0 + gemmO c0
    cudaStreamWaitEvent(s1, evKV, 0);
    attn_kernel<<<dim3(SL / 128, NH, 4), blk, AT_SMEM, s1>>>(4);
    cudaEventRecord(evA1, s1);

    // main: attn batches 0..3 (needs gemmQ), then gemmO halves
    cudaStreamWaitEvent(0, evGQ, 0);
    attn_kernel<<<dim3(SL / 128, NH, 4), blk, AT_SMEM>>>(0);
    gemm_out<<<ggh, gblk, GSMEM>>>(ao, wo16, bo, out, 0);
    cudaStreamWaitEvent(0, evA1, 0);
    gemm_out<<<ggh, gblk, GSMEM>>>(ao, wo16, bo, out, MT / 256);
}

// round 17
// speedup vs baseline: 1.0232x; 1.0232x over previous
#include <cuda_runtime.h>
#include <cuda_fp16.h>
#include <math.h>
#include <stdint.h>

#define NB 8
#define SL 8192
#define ED 512
#define NH 8
#define DH 64
#define MT (NB*SL)

// ---------------- scratch (device globals; no allocation) -------------------
__device__ float g_kv[NB * NH * DH * DH];
__device__ float g_ksum[NB * NH * DH];
__device__ __half g_qh[(size_t)MT * ED];
__device__ __half g_k16[(size_t)MT * ED];
__device__ __half g_v16[(size_t)MT * ED];
__device__ __half g_ao[(size_t)MT * ED];
__device__ __half g_w16[4][ED * ED];
__device__ __half g_kvah[NB * NH * 80 * 64];
__device__ __half g_kval[NB * NH * 80 * 64];

// ---------------- helpers ---------------------------------------------------
__device__ __forceinline__ uint32_t smem_u32(const void* p) {
    uint32_t a;
    asm("{ .reg .u64 t; cvta.to.shared.u64 t, %1; cvt.u32.u64 %0, t; }" : "=r"(a) : "l"(p));
    return a;
}
__device__ __forceinline__ uint32_t pack2h(__half a, __half b) {
    __half2 t(a, b);
    return *reinterpret_cast<uint32_t*>(&t);
}
__device__ __forceinline__ void cp16(uint32_t s, const void* g) {
    asm volatile("cp.async.cg.shared.global [%0], [%1], 16;" :: "r"(s), "l"(g));
}
#define CP_COMMIT() asm volatile("cp.async.commit_group;" ::: "memory")
#define CP_WAIT(N)  asm volatile("cp.async.wait_group %0;" :: "n"(N) : "memory")

#define LDSM4(r, addr)                                                         \
    asm volatile("ldmatrix.sync.aligned.m8n8.x4.shared.b16 {%0,%1,%2,%3}, [%4];" \
        : "=r"((r)[0]), "=r"((r)[1]), "=r"((r)[2]), "=r"((r)[3]) : "r"(addr))

__device__ __forceinline__ uint32_t movm(uint32_t a) {
    uint32_t d;
    asm volatile("movmatrix.sync.aligned.m8n8.trans.b16 %0, %1;" : "=r"(d) : "r"(a));
    return d;
}

#define MMA16816(d, a, b0, b1)                                                 \
    asm volatile("mma.sync.aligned.m16n8k16.row.col.f32.f16.f16.f32 "          \
        "{%0,%1,%2,%3}, {%4,%5,%6,%7}, {%8,%9}, {%0,%1,%2,%3};"                \
        : "+f"((d)[0]), "+f"((d)[1]), "+f"((d)[2]), "+f"((d)[3])               \
        : "r"((a)[0]), "r"((a)[1]), "r"((a)[2]), "r"((a)[3]), "r"(b0), "r"(b1))

// ---------------- fused weight convert: all 4 W in one launch -----------------
__global__ __launch_bounds__(256) void conv4_kernel(const float* __restrict__ w0,
                                                    const float* __restrict__ w1,
                                                    const float* __restrict__ w2,
                                                    const float* __restrict__ w3,
                                                    int n4)
{
    const int wsel = blockIdx.y;
    const float* src = (wsel == 0) ? w0 : (wsel == 1) ? w1 : (wsel == 2) ? w2 : w3;
    __half* dst = g_w16[wsel];
    int i = blockIdx.x * blockDim.x + threadIdx.x;
    if (i >= n4) return;
    float4 v = ((const float4*)src)[i];
    uint2 p;
    p.x = pack2h(__float2half_rn(v.x), __float2half_rn(v.y));
    p.y = pack2h(__float2half_rn(v.z), __float2half_rn(v.w));
    ((uint2*)dst)[i] = p;
}

// ---------------- shared GEMM fragment compute --------------------------------
__device__ __forceinline__ void gemm_compute_chunk(uint32_t sA, uint32_t sB,
                                                   int lane, int wm, int wn,
                                                   float acc[2][8][4])
{
    uint32_t fa[2][2][4];
    uint32_t fb[2][4];

    #define LOAD_A(s16, buf)                                                   \
    {                                                                          \
        _Pragma("unroll")                                                      \
        for (int mf = 0; mf < 2; mf++) {                                       \
            const int arow = wm * 32 + mf * 16 + (lane & 15);                  \
            const int achk = (s16) * 2 + (lane >> 4);                          \
            LDSM4(fa[buf][mf], sA + arow * 128 + ((achk ^ (arow & 7)) << 4));  \
        }                                                                      \
    }
    #define LOAD_B(s16, nf, buf)                                               \
    {                                                                          \
        const int brow = wn * 64 + (nf) * 16 + (lane & 7) + ((lane >> 4) << 3);\
        const int bchk = (s16) * 2 + ((lane >> 3) & 1);                        \
        LDSM4(fb[buf], sB + brow * 128 + ((bchk ^ (brow & 7)) << 4));          \
    }

    LOAD_A(0, 0);
    LOAD_B(0, 0, 0);

#pragma unroll
    for (int s16 = 0; s16 < 4; s16++) {
        const int ab = s16 & 1;
#pragma unroll
        for (int nf = 0; nf < 4; nf++) {
            const int bb = nf & 1;
            if (nf < 3) {
                LOAD_B(s16, nf + 1, bb ^ 1);
            } else if (s16 < 3) {
                LOAD_A(s16 + 1, ab ^ 1);
                LOAD_B(s16 + 1, 0, bb ^ 1);
            }
#pragma unroll
            for (int mf = 0; mf < 2; mf++) {
                MMA16816(acc[mf][2 * nf],     fa[ab][mf], fb[bb][0], fb[bb][1]);
                MMA16816(acc[mf][2 * nf + 1], fa[ab][mf], fb[bb][2], fb[bb][3]);
            }
        }
    }
    #undef LOAD_A
    #undef LOAD_B
}

// ---------------- f32-A fused-convert GEMM (proven R14) -----------------------
#define RAW2_OFF 0
#define AH2_OFF  32768
#define B2_OFF   49152
#define STAGE2   81920
#define GSMEM2   (2 * STAGE2)

__device__ __forceinline__ void issue_f32(uint32_t st, const float* __restrict__ A,
                                          const __half* __restrict__ Bh,
                                          int bm, int bn, int ch, int tid)
{
    const int kc = ch * 64;
#pragma unroll
    for (int i = 0; i < 4; i++) {
        const int idx = tid + i * 512;
        const int row = idx >> 4;
        const int c16 = idx & 15;
        cp16(st + RAW2_OFF + idx * 16,
             A + (size_t)(bm + row) * ED + kc + c16 * 4);
    }
#pragma unroll
    for (int i = 0; i < 4; i++) {
        const int idx = tid + i * 512;
        const int row = idx >> 3;
        const int c = idx & 7;
        cp16(st + B2_OFF + row * 128 + ((c ^ (row & 7)) << 4),
             Bh + (size_t)(bn + row) * ED + kc + c * 8);
    }
    CP_COMMIT();
}

__device__ __forceinline__ void convert_own(char* smem_raw, uint32_t stoff, int tid)
{
#pragma unroll
    for (int i = 0; i < 4; i++) {
        const int idx = tid + i * 512;
        const int row = idx >> 4;
        const int c16 = idx & 15;
        float4 v = *(const float4*)(smem_raw + stoff + RAW2_OFF + idx * 16);
        uint2 p;
        p.x = pack2h(__float2half_rn(v.x), __float2half_rn(v.y));
        p.y = pack2h(__float2half_rn(v.z), __float2half_rn(v.w));
        const int c8 = c16 >> 1;
        const uint32_t soff = row * 128 + ((c8 ^ (row & 7)) << 4) + (c16 & 1) * 8;
        *(uint2*)(smem_raw + stoff + AH2_OFF + soff) = p;
    }
}

template <int FEAT>
__device__ __forceinline__ void gemm_f32_body(const float* __restrict__ A,
                                              const __half* __restrict__ Bh,
                                              const float* __restrict__ bias,
                                              __half* __restrict__ Ch,
                                              char* smem_raw)
{
    const uint32_t sb = smem_u32(smem_raw);
    const int tid = threadIdx.x;
    const int lane = tid & 31;
    const int wid = tid >> 5;
    const int wm = wid >> 2;
    const int wn = wid & 3;
    const int bm = blockIdx.y * 128;
    const int bn = blockIdx.x * 256;

    float acc[2][8][4];
#pragma unroll
    for (int i = 0; i < 2; i++)
#pragma unroll
        for (int j = 0; j < 8; j++)
#pragma unroll
            for (int q = 0; q < 4; q++) acc[i][j][q] = 0.f;

    issue_f32(sb, A, Bh, bm, bn, 0, tid);
    issue_f32(sb + STAGE2, A, Bh, bm, bn, 1, tid);

#pragma unroll 1
    for (int ch = 0; ch < 8; ch++) {
        const uint32_t stoff = (ch & 1) * STAGE2;
        if (ch < 7) { CP_WAIT(1); } else { CP_WAIT(0); }
        convert_own(smem_raw, stoff, tid);
        __syncthreads();
        gemm_compute_chunk(sb + stoff + AH2_OFF, sb + stoff + B2_OFF,
                           lane, wm, wn, acc);
        __syncthreads();
        if (ch + 2 < 8) issue_f32(sb + stoff, A, Bh, bm, bn, ch + 2, tid);
    }

#pragma unroll
    for (int mf = 0; mf < 2; mf++) {
        const int row0 = bm + wm * 32 + mf * 16 + (lane >> 2);
#pragma unroll
        for (int nf8 = 0; nf8 < 8; nf8++) {
            const int col = bn + wn * 64 + nf8 * 8 + (lane & 3) * 2;
            const float b0 = bias[col], b1 = bias[col + 1];
            float x0 = acc[mf][nf8][0] + b0;
            float x1 = acc[mf][nf8][1] + b1;
            float x2 = acc[mf][nf8][2] + b0;
            float x3 = acc[mf][nf8][3] + b1;
            if (FEAT) {
                x0 = (x0 > 0.f) ? (x0 + 1.f) : expf(x0);
                x1 = (x1 > 0.f) ? (x1 + 1.f) : expf(x1);
                x2 = (x2 > 0.f) ? (x2 + 1.f) : expf(x2);
                x3 = (x3 > 0.f) ? (x3 + 1.f) : expf(x3);
            }
            *(uint32_t*)&Ch[(size_t)row0 * ED + col] =
                pack2h(__float2half_rn(x0), __float2half_rn(x1));
            *(uint32_t*)&Ch[(size_t)(row0 + 8) * ED + col] =
                pack2h(__float2half_rn(x2), __float2half_rn(x3));
        }
    }
}

__global__ __launch_bounds__(512, 1) void gemm_q_f32(const float* __restrict__ A,
                                                     const __half* __restrict__ Bh,
                                                     const float* __restrict__ bias,
                                                     __half* __restrict__ Ch)
{
    extern __shared__ char smem_raw[];
    gemm_f32_body<1>(A, Bh, bias, Ch, smem_raw);
}

__global__ __launch_bounds__(512, 1) void gemm_kv_f32(const float* __restrict__ Ak,
                                                      const float* __restrict__ Av,
                                                      const __half* __restrict__ Bk,
                                                      const __half* __restrict__ Bv,
                                                      const float* __restrict__ biask,
                                                      const float* __restrict__ biasv,
                                                      __half* __restrict__ Ck,
                                                      __half* __restrict__ Cv)
{
    extern __shared__ char smem_raw[];
    if (blockIdx.z == 0)
        gemm_f32_body<1>(Ak, Bk, biask, Ck, smem_raw);
    else
        gemm_f32_body<0>(Av, Bv, biasv, Cv, smem_raw);
}

// ---------------- fp16-A GEMM for output (proven, 3-stage) --------------------
#define A_OFF    0
#define B_OFF    16384
#define STAGE_SZ 49152
#define GSMEM    (3 * STAGE_SZ)

__device__ __forceinline__ void issue_loads(uint32_t st,
                                            const __half* __restrict__ A16,
                                            const __half* __restrict__ Bh,
                                            int bm, int bn, int ch, int tid)
{
    const int kc = ch * 64;
#pragma unroll
    for (int i = 0; i < 2; i++) {
        const int idx = tid + i * 512;
        const int row = idx >> 3;
        const int c = idx & 7;
        cp16(st + A_OFF + row * 128 + ((c ^ (row & 7)) << 4),
             A16 + (size_t)(bm + row) * ED + kc + c * 8);
    }
#pragma unroll
    for (int i = 0; i < 4; i++) {
        const int idx = tid + i * 512;
        const int row = idx >> 3;
        const int c = idx & 7;
        cp16(st + B_OFF + row * 128 + ((c ^ (row & 7)) << 4),
             Bh + (size_t)(bn + row) * ED + kc + c * 8);
    }
    CP_COMMIT();
}

__global__ __launch_bounds__(512, 1) void gemm_out(const __half* __restrict__ A16,
                                                   const __half* __restrict__ Bh,
                                                   const float* __restrict__ bias,
                                                   float* __restrict__ C)
{
    extern __shared__ char smem_raw[];
    const uint32_t sb = smem_u32(smem_raw);
    const int tid = threadIdx.x;
    const int lane = tid & 31;
    const int wid = tid >> 5;
    const int wm = wid >> 2;
    const int wn = wid & 3;
    const int bm = blockIdx.y * 128;
    const int bn = blockIdx.x * 256;

    float acc[2][8][4];
#pragma unroll
    for (int i = 0; i < 2; i++)
#pragma unroll
        for (int j = 0; j < 8; j++)
#pragma unroll
            for (int q = 0; q < 4; q++) acc[i][j][q] = 0.f;

    issue_loads(sb, A16, Bh, bm, bn, 0, tid);
    issue_loads(sb + STAGE_SZ, A16, Bh, bm, bn, 1, tid);

#pragma unroll 1
    for (int ch = 0; ch < 8; ch++) {
        if (ch < 7) { CP_WAIT(1); } else { CP_WAIT(0); }
        __syncthreads();
        if (ch < 6)
            issue_loads(sb + ((ch + 2) % 3) * STAGE_SZ, A16, Bh, bm, bn, ch + 2, tid);
        const uint32_t cur = sb + (ch % 3) * STAGE_SZ;
        gemm_compute_chunk(cur + A_OFF, cur + B_OFF, lane, wm, wn, acc);
    }

#pragma unroll
    for (int mf = 0; mf < 2; mf++) {
        const int row0 = bm + wm * 32 + mf * 16 + (lane >> 2);
#pragma unroll
        for (int nf8 = 0; nf8 < 8; nf8++) {
            const int col = bn + wn * 64 + nf8 * 8 + (lane & 3) * 2;
            const float b0 = bias[col], b1 = bias[col + 1];
            *(float2*)&C[(size_t)row0 * ED + col] =
                make_float2(acc[mf][nf8][0] + b0, acc[mf][nf8][1] + b1);
            *(float2*)&C[(size_t)(row0 + 8) * ED + col] =
                make_float2(acc[mf][nf8][2] + b0, acc[mf][nf8][3] + b1);
        }
    }
}

// ---------------- zeroing ----------------------------------------------------
__global__ void zero_small()
{
    int i = blockIdx.x * blockDim.x + threadIdx.x;
    if (i < NB * NH * DH * DH) g_kv[i] = 0.f;
    if (i < NB * NH * DH)      g_ksum[i] = 0.f;
}

// ---------------- tensorized KV via movmatrix (proven R12) --------------------
#define KV2_K 0
#define KV2_V 8192
#define KV2_STAGE 16384
#define KV2_SMEM  32768

__device__ __forceinline__ void kv_issue(uint32_t sb, int stage, int n, int h,
                                         int s0, int tid)
{
#pragma unroll
    for (int it = 0; it < 4; it++) {
        const int idx = tid + it * 256;
        const int t = idx >> 9;
        const int r = (idx >> 3) & 63;
        const int c = idx & 7;
        const __half* src = t ? g_v16 : g_k16;
        cp16(sb + stage * KV2_STAGE + t * 8192 + r * 128 + ((c ^ (r & 7)) << 4),
             src + (size_t)(n * SL + s0 + r) * ED + h * DH + c * 8);
    }
    CP_COMMIT();
}

__global__ __launch_bounds__(256) void kv_kernel()
{
    extern __shared__ char smem_raw[];
    const uint32_t sb = smem_u32(smem_raw);
    const int tid = threadIdx.x;
    const int lane = tid & 31;
    const int wid = tid >> 5;
    const int wm = wid & 3;
    const int wn = wid >> 2;
    const int sp = blockIdx.x;
    const int h = blockIdx.y;
    const int n = blockIdx.z;
    const int nh = n * NH + h;
    const int s_base = sp * (SL / 8);

    float acc[4][4];
#pragma unroll
    for (int j = 0; j < 4; j++)
#pragma unroll
        for (int q = 0; q < 4; q++) acc[j][q] = 0.f;
    float ks = 0.f;
    const int sum_d = tid & 63;
    const int sum_p = tid >> 6;

    kv_issue(sb, 0, n, h, s_base, tid);

#pragma unroll 1
    for (int it = 0; it < 16; it++) {
        if (it < 15) { kv_issue(sb, (it + 1) & 1, n, h, s_base + (it + 1) * 64, tid); CP_WAIT(1); }
        else CP_WAIT(0);
        __syncthreads();
        const uint32_t st = sb + (it & 1) * KV2_STAGE;
        char* stc = smem_raw + (it & 1) * KV2_STAGE;

#pragma unroll
        for (int kstep = 0; kstep < 4; kstep++) {
            uint32_t vr[4], fa[4];
            {
                const int arow = kstep * 16 + (lane & 15);
                const int achk = wm * 2 + (lane >> 4);
                LDSM4(vr, st + KV2_V + arow * 128 + ((achk ^ (arow & 7)) << 4));
                fa[0] = movm(vr[0]); fa[1] = movm(vr[2]);
                fa[2] = movm(vr[1]); fa[3] = movm(vr[3]);
            }
#pragma unroll
            for (int p = 0; p < 2; p++) {
                uint32_t kr[4];
                const int brow = kstep * 16 + (lane & 15);
                const int bchk = wn * 4 + p * 2 + (lane >> 4);
                LDSM4(kr, st + KV2_K + brow * 128 + ((bchk ^ (brow & 7)) << 4));
                uint32_t b00 = movm(kr[0]), b01 = movm(kr[1]);
                uint32_t b10 = movm(kr[2]), b11 = movm(kr[3]);
                MMA16816(acc[p * 2],     fa, b00, b01);
                MMA16816(acc[p * 2 + 1], fa, b10, b11);
            }
        }
#pragma unroll
        for (int rr = 0; rr < 16; rr++) {
            const int r = sum_p * 16 + rr;
            uint32_t off = r * 128 + sum_d * 2;
            uint32_t sw = off ^ ((off >> 3) & 0x70);
            ks += __half2float(*(__half*)(stc + KV2_K + sw));
        }
        __syncthreads();
    }

    const int g = lane >> 2, tig = lane & 3;
    float* kvout = g_kv + nh * 4096;
#pragma unroll
    for (int j = 0; j < 4; j++) {
        const int d = wn * 32 + j * 8 + tig * 2;
        const int m = wm * 16 + g;
        atomicAdd(&kvout[m * 64 + d],           acc[j][0]);
        atomicAdd(&kvout[m * 64 + d + 1],       acc[j][1]);
        atomicAdd(&kvout[(m + 8) * 64 + d],     acc[j][2]);
        atomicAdd(&kvout[(m + 8) * 64 + d + 1], acc[j][3]);
    }
    atomicAdd(&g_ksum[nh * 64 + sum_d], ks);
}

// ---------------- KV finalize -------------------------------------------------
__global__ __launch_bounds__(256) void kv_finalize()
{
    const int nh = blockIdx.x;
    const float* kv = g_kv + nh * 4096;
    const float* ks = g_ksum + nh * 64;
    char* oh = (char*)g_kvah + (size_t)nh * 10240;
    char* ol = (char*)g_kval + (size_t)nh * 10240;
    for (int idx = threadIdx.x; idx < 80 * 64; idx += 256) {
        const int r = idx >> 6, d = idx & 63;
        float x = (r < 64) ? kv[r * 64 + d] : (r == 64 ? ks[d] : 0.f);
        __half hh = __float2half_rn(x);
        __half ll = __float2half_rn(x - __half2float(hh));
        uint32_t off = r * 128 + d * 2;
        uint32_t sw = off ^ ((off >> 3) & 0x70);
        *(__half*)(oh + sw) = hh;
        *(__half*)(ol + sw) = ll;
    }
}

// ---------------- tensorized attn (proven R13) --------------------------------
#define AT_Q  0
#define AT_BH 16384
#define AT_BL 26624
#define AT_SMEM 36864

__global__ __launch_bounds__(256) void attn_kernel()
{
    extern __shared__ char smem_raw[];
    const uint32_t sb = smem_u32(smem_raw);
    const int tid = threadIdx.x;
    const int lane = tid & 31;
    const int wid = tid >> 5;
    const int l0 = blockIdx.x * 128;
    const int h = blockIdx.y;
    const int n = blockIdx.z;
    const int nh = n * NH + h;

#pragma unroll
    for (int it = 0; it < 4; it++) {
        int idx = tid + it * 256;
        int r = idx >> 3;
        int c = idx & 7;
        cp16(sb + AT_Q + r * 128 + ((c ^ (r & 7)) << 4),
             g_qh + (size_t)(n * SL + l0 + r) * ED + h * DH + c * 8);
    }
#pragma unroll
    for (int it = 0; it < 5; it++) {
        int idx = tid + it * 256;
        int buf = idx >= 640;
        int ch = buf ? idx - 640 : idx;
        cp16(sb + (buf ? AT_BL : AT_BH) + ch * 16,
             (buf ? g_kval : g_kvah) + (size_t)nh * 5120 + ch * 8);
    }
    CP_COMMIT();
    CP_WAIT(0);
    __syncthreads();

    float acc[9][4];
#pragma unroll
    for (int j = 0; j < 9; j++)
#pragma unroll
        for (int q = 0; q < 4; q++) acc[j][q] = 0.f;

#pragma unroll
    for (int kstep = 0; kstep < 4; kstep++) {
        uint32_t fah[4];
        {
            const int arow = wid * 16 + (lane & 15);
            const int achk = kstep * 2 + (lane >> 4);
            LDSM4(fah, sb + AT_Q + arow * 128 + ((achk ^ (arow & 7)) << 4));
        }
        uint32_t fbh[5][4], fbl[5][4];
#pragma unroll
        for (int p = 0; p < 5; p++) {
            const int brow = p * 16 + (lane & 7) + ((lane >> 4) << 3);
            const int bchk = kstep * 2 + ((lane >> 3) & 1);
            const uint32_t boff = brow * 128 + ((bchk ^ (brow & 7)) << 4);
            LDSM4(fbh[p], sb + AT_BH + boff);
            LDSM4(fbl[p], sb + AT_BL + boff);
        }
#pragma unroll
        for (int j = 0; j < 9; j++) {
            uint32_t bh0 = fbh[j >> 1][(j & 1) * 2], bh1 = fbh[j >> 1][(j & 1) * 2 + 1];
            uint32_t bl0 = fbl[j >> 1][(j & 1) * 2], bl1 = fbl[j >> 1][(j & 1) * 2 + 1];
            MMA16816(acc[j], fah, bh0, bh1);
            MMA16816(acc[j], fah, bl0, bl1);
        }
    }

    const float zd0 = __shfl_sync(0xFFFFFFFFu, acc[8][0], lane & ~3);
    const float zd1 = __shfl_sync(0xFFFFFFFFu, acc[8][2], lane & ~3);
    const float z0 = 1.f / (fmaxf(zd0, 0.f) + 1e-6f);
    const float z1 = 1.f / (fmaxf(zd1, 0.f) + 1e-6f);
    const int g = lane >> 2, tig = lane & 3;
    const int row0 = l0 + wid * 16 + g;

#pragma unroll
    for (int j = 0; j < 8; j++) {
        const int e = h * DH + j * 8 + tig * 2;
        float x0 = acc[j][0] * z0, x1 = acc[j][1] * z0;
        float x2 = acc[j][2] * z1, x3 = acc[j][3] * z1;
        *(uint32_t*)&g_ao[(size_t)(n * SL + row0) * ED + e] =
            pack2h(__float2half_rn(x0), __float2half_rn(x1));
        *(uint32_t*)&g_ao[(size_t)(n * SL + row0 + 8) * ED + e] =
            pack2h(__float2half_rn(x2), __float2half_rn(x3));
    }
}

// ---------------- launch -----------------------------------------------------
extern "C" void kernel_launch(void* const* d_in, const int* in_sizes, int n_in,
                              void* d_out, int out_size)
{
    const float* q_in = (const float*)d_in[0];
    const float* k_in = (const float*)d_in[1];
    const float* v_in = (const float*)d_in[2];
    const float* Wq = (const float*)d_in[3];
    const float* bq = (const float*)d_in[4];
    const float* Wk = (const float*)d_in[5];
    const float* bk = (const float*)d_in[6];
    const float* Wv = (const float*)d_in[7];
    const float* bv = (const float*)d_in[8];
    const float* Wo = (const float*)d_in[9];
    const float* bo = (const float*)d_in[10];
    float* out = (float*)d_out;

    __half *qh, *k16, *v16, *ao, *w16;
    cudaGetSymbolAddress((void**)&qh, g_qh);
    cudaGetSymbolAddress((void**)&k16, g_k16);
    cudaGetSymbolAddress((void**)&v16, g_v16);
    cudaGetSymbolAddress((void**)&ao, g_ao);
    cudaGetSymbolAddress((void**)&w16, g_w16);
    __half* wq16 = w16;
    __half* wk16 = w16 + (size_t)ED * ED;
    __half* wv16 = w16 + (size_t)2 * ED * ED;
    __half* wo16 = w16 + (size_t)3 * ED * ED;

    static cudaStream_t s1, s3;
    static cudaEvent_t ev0, evW, evGQ;
    static bool inited = false;
    if (!inited) {
        cudaStreamCreateWithFlags(&s1, cudaStreamNonBlocking);
        cudaStreamCreateWithFlags(&s3, cudaStreamNonBlocking);
        cudaEventCreateWithFlags(&ev0, cudaEventDisableTiming);
        cudaEventCreateWithFlags(&evW, cudaEventDisableTiming);
        cudaEventCreateWithFlags(&evGQ, cudaEventDisableTiming);
        cudaFuncSetAttribute(gemm_q_f32,  cudaFuncAttributeMaxDynamicSharedMemorySize, GSMEM2);
        cudaFuncSetAttribute(gemm_kv_f32, cudaFuncAttributeMaxDynamicSharedMemorySize, GSMEM2);
        cudaFuncSetAttribute(gemm_out,    cudaFuncAttributeMaxDynamicSharedMemorySize, GSMEM);
        cudaFuncSetAttribute(kv_kernel,   cudaFuncAttributeMaxDynamicSharedMemorySize, KV2_SMEM);
        cudaFuncSetAttribute(attn_kernel, cudaFuncAttributeMaxDynamicSharedMemorySize, AT_SMEM);
        inited = true;
    }

    const int n4w = ED * ED / 4;
    dim3 blk(256);
    dim3 gblk(512);
    dim3 gg(ED / 256, MT / 128);
    dim3 gg2(ED / 256, MT / 128, 2);

    // fork: single fused weight-convert launch + zero on side stream
    cudaEventRecord(ev0, 0);
    cudaStreamWaitEvent(s3, ev0, 0);
    cudaStreamWaitEvent(s1, ev0, 0);
    conv4_kernel<<<dim3((n4w + 255) / 256, 4), blk, 0, s3>>>(Wq, Wk, Wv, Wo, n4w);
    zero_small<<<(NB * NH * DH * DH + 255) / 256, 256, 0, s3>>>();
    cudaEventRecord(evW, s3);

    // main: gemmKV first (kv depends on it)
    cudaStreamWaitEvent(0, evW, 0);
    gemm_kv_f32<<<gg2, gblk, GSMEM2>>>(k_in, v_in, wk16, wv16, bk, bv, k16, v16);

    // s1: gemmQ concurrent — kv+finalize hide under its tail
    cudaStreamWaitEvent(s1, evW, 0);
    gemm_q_f32<<<gg, gblk, GSMEM2, s1>>>(q_in, wq16, bq, qh);
    cudaEventRecord(evGQ, s1);

    // main: kv + finalize (overlap gemmQ), then attn (needs Q), output GEMM
    kv_kernel<<<dim3(8, NH, NB), blk, KV2_SMEM>>>();
    kv_finalize<<<NB * NH, blk>>>();
    cudaStreamWaitEvent(0, evGQ, 0);
    attn_kernel<<<dim3(SL / 128, NH, NB), blk, AT_SMEM>>>();
    gemm_out<<<gg, gblk, GSMEM>>>(ao, wo16, bo, out);
}